// round 15
// baseline (speedup 1.0000x reference)
#include <cuda_runtime.h>
#include <cuda_bf16.h>
#include <cstdint>

// GDLoss: elementwise Gaussian KL loss over [N,5] xywhr boxes. 176MB traffic.
// R15 = R14 (register double-buffered persistent loop: 2 boxes/thread/iter,
// next iteration's 10 LDG.64 prefetched under current iteration's math; no
// smem, no barriers; kernel 29.0us @ DRAM 74.2% with only 40.7% occ) with the
// wave-quantization defect fixed: grid = 608 = exactly 4 resident blocks/SM
// x 152 SMs = ONE persistent wave (R14 ran 1064 blocks = 1.75 waves, so the
// partial second wave idled SMs at the tail). Plus strength-reduced pointers
// in the loop body.

#define TAU_F   1.0f
#define EPS_F   1e-6f
#define BLK     256
#define GRID_P  608                  // 4 blocks/SM * 152 SMs: one wave exactly

__device__ __forceinline__ float rcp_fast(float x) {
    float r; asm("rcp.approx.f32 %0, %1;" : "=f"(r) : "f"(x)); return r;
}
__device__ __forceinline__ float sqrt_fast(float x) {
    float r; asm("sqrt.approx.f32 %0, %1;" : "=f"(r) : "f"(x)); return r;
}

// loss for one box pair (algebraically reduced):
//   det_t = tww*thh/16, det_p = pww*phh/16     (rotation-invariant, no trig)
//   t1num = ths(dx^2+dy^2) - thd(c2t(dx^2-dy^2) + 2 s2t dx dy)
//   n2num = 2(ths*phs - thd*phd*cos(2rt-2rp))
//   dis   = (t1num+n2num)*16/(tww*thh) + log((tww*thh)/(pww*phh)) - 2
__device__ __forceinline__ float gd_loss_one(
    float px, float py, float pw, float ph, float prr,
    float tx, float ty, float tw, float th, float trr)
{
    pw = fminf(fmaxf(pw, 1e-7f), 1e7f);
    ph = fminf(fmaxf(ph, 1e-7f), 1e7f);
    tw = fminf(fmaxf(tw, 1e-7f), 1e7f);
    th = fminf(fmaxf(th, 1e-7f), 1e7f);

    const float pww = pw * pw, phh = ph * ph;
    const float tww = tw * tw, thh = th * th;

    const float phs = 0.125f * (pww + phh);
    const float phd = 0.125f * (pww - phh);
    const float ths = 0.125f * (tww + thh);
    const float thd = 0.125f * (tww - thh);

    float s2t, c2t;
    __sincosf(2.0f * trr, &s2t, &c2t);
    const float cdd = __cosf(2.0f * (trr - prr));   // cos(2rt - 2rp)

    const float dx = px - tx;
    const float dy = py - ty;
    const float dx2 = dx * dx, dy2 = dy * dy;
    const float sum2 = dx2 + dy2, dif2 = dx2 - dy2;
    const float dxy = dx * dy;

    const float rot   = fmaf(c2t, dif2, 2.0f * s2t * dxy);
    const float t1num = fmaf(ths, sum2, -thd * rot);
    const float n2num = 2.0f * fmaf(-thd * phd, cdd, ths * phs);

    const float dtt = tww * thh;                    // 16*det_t
    const float dpp = pww * phh;                    // 16*det_p
    const float invdt16 = 16.0f * rcp_fast(dtt);
    const float logterm = __logf(dtt * rcp_fast(dpp));

    const float dis = fmaf(t1num + n2num, invdt16, logterm - 2.0f);
    const float kl = fmaxf(dis, EPS_F);
    return 1.0f - rcp_fast(TAU_F + sqrt_fast(kl));
}

struct Pair10 {                       // 10 floats = one 2-box record
    float2 a, b, c, d, e;
};

__device__ __forceinline__ Pair10 load_pair(const float2* __restrict__ base) {
    Pair10 r;
    r.a = base[0]; r.b = base[1]; r.c = base[2]; r.d = base[3]; r.e = base[4];
    return r;
}

// compute both losses of a pair record:
//   box0 = (a.x a.y b.x b.y c.x), box1 = (c.y d.x d.y e.x e.y)
__device__ __forceinline__ float2 pair_loss(const Pair10& p, const Pair10& t) {
    float2 r;
    r.x = gd_loss_one(p.a.x, p.a.y, p.b.x, p.b.y, p.c.x,
                      t.a.x, t.a.y, t.b.x, t.b.y, t.c.x);
    r.y = gd_loss_one(p.c.y, p.d.x, p.d.y, p.e.x, p.e.y,
                      t.c.y, t.d.x, t.d.y, t.e.x, t.e.y);
    return r;
}

__global__ void __launch_bounds__(BLK, 4) gd_loss_kernel(
    const float* __restrict__ pred,
    const float* __restrict__ target,
    float* __restrict__ out,
    int n)
{
    const int npairs = n >> 1;                        // full 2-box pairs
    const int stride = gridDim.x * BLK;               // in pair units
    int i = blockIdx.x * BLK + threadIdx.x;

    // Handle odd trailing box (n odd) with the first thread.
    if ((n & 1) && (blockIdx.x == 0) && (threadIdx.x == 0)) {
        const float* p = pred   + (size_t)(n - 1) * 5;
        const float* t = target + (size_t)(n - 1) * 5;
        out[n - 1] = gd_loss_one(p[0], p[1], p[2], p[3], p[4],
                                 t[0], t[1], t[2], t[3], t[4]);
    }

    if (i >= npairs) return;

    // Strength-reduced pointers: advance by ptrStep float2 per iteration.
    const float2* __restrict__ pp = (const float2*)pred   + (size_t)i * 5;
    const float2* __restrict__ tp = (const float2*)target + (size_t)i * 5;
    float2* __restrict__ op = (float2*)out + i;
    const size_t ptrStep = (size_t)stride * 5;

    // Prime: load current pair's 10 float2.
    Pair10 pc = load_pair(pp);
    Pair10 tc = load_pair(tp);

    for (;;) {
        const int inext = i + stride;
        if (inext < npairs) {
            // Prefetch next iteration (10 independent LDG.64) BEFORE compute;
            // no dependency on pc/tc so these fly during the math below.
            Pair10 pn = load_pair(pp + ptrStep);
            Pair10 tn = load_pair(tp + ptrStep);

            *op = pair_loss(pc, tc);

            pc = pn; tc = tn;
            i = inext; pp += ptrStep; tp += ptrStep; op += stride;
        } else {
            *op = pair_loss(pc, tc);
            break;
        }
    }
}

extern "C" void kernel_launch(void* const* d_in, const int* in_sizes, int n_in,
                              void* d_out, int out_size)
{
    const float* pred   = (const float*)d_in[0];
    const float* target = (const float*)d_in[1];
    // d_in[2] (weight) is unused by the reference computation (LOSS_WEIGHT=1).
    float* out = (float*)d_out;

    const int n = out_size;                      // N boxes; output [N,1] floats
    const int npairs = n >> 1;                   // 2M for N=4M
    int grid = GRID_P;
    const int maxGrid = (npairs + BLK - 1) / BLK;
    if (grid > maxGrid && maxGrid > 0) grid = maxGrid;
    if (grid < 1) grid = 1;
    gd_loss_kernel<<<grid, BLK>>>(pred, target, out, n);
}